// round 1
// baseline (speedup 1.0000x reference)
#include <cuda_runtime.h>
#include <math.h>

#define SEQ  2048
#define HDIM 1024
#define GDIM 4096   // 4*H
#define NCLS 512
#define NB   128    // scan grid (<= SM count -> all resident)

// ---------------- scratch (static device globals; no allocation) ----------------
__device__ float    g_gx[SEQ * GDIM];      // 32 MB: precomputed input gates
__device__ float    g_seqA[SEQ * HDIM];    // 8 MB: layer output ping
__device__ float    g_seqB[SEQ * HDIM];    // 8 MB: layer output pong
__device__ float    g_Wt[HDIM * GDIM];     // 16 MB: transposed weight (max size)
__device__ float    g_zero[HDIM];          // stays zero (h_{-1})
__device__ float    g_bzero[GDIM];         // stays zero (dummy 2nd bias)
__device__ unsigned g_counts[SEQ];         // per-step barrier counters

// ---------------- transpose: Wt[c][r] = W[r][c] ----------------
__global__ void transpose_k(const float* __restrict__ W, float* __restrict__ Wt,
                            int R, int C) {
    __shared__ float tile[32][33];
    int c0 = blockIdx.x * 32, r0 = blockIdx.y * 32;
    int x = threadIdx.x, y = threadIdx.y;
#pragma unroll
    for (int j = 0; j < 32; j += 8)
        tile[y + j][x] = W[(size_t)(r0 + y + j) * C + (c0 + x)];
    __syncthreads();
#pragma unroll
    for (int j = 0; j < 32; j += 8)
        Wt[(size_t)(c0 + y + j) * R + (r0 + x)] = tile[x][y + j];
}

// ---------------- zero barrier counters ----------------
__global__ void zero_k(unsigned* p, int n) {
    int i = blockIdx.x * 256 + threadIdx.x;
    if (i < n) p[i] = 0;
}

// ---------------- SGEMM: C[M,N] = A[M,K] @ B[K,N] + b1[N] + b2[N] ----------------
// BM=BN=128, BK=8, 256 threads, 8x8 per thread (split 4+4 to avoid LDS conflicts).
__global__ void __launch_bounds__(256) sgemm_bias_k(
    const float* __restrict__ A, const float* __restrict__ B,
    const float* __restrict__ b1, const float* __restrict__ b2,
    float* __restrict__ C, int M, int N, int K) {
    __shared__ float As[8][128];
    __shared__ float Bs[8][128];
    const int tid  = threadIdx.x;
    const int tx   = tid & 15;        // col group 0..15
    const int ty   = tid >> 4;        // row group 0..15
    const int brow = blockIdx.y * 128;
    const int bcol = blockIdx.x * 128;

    const int ar  = tid >> 1;         // A tile row 0..127
    const int ak  = (tid & 1) * 4;    // A tile k offset 0 or 4
    const int bkk = tid >> 5;         // B tile k 0..7
    const int bn  = (tid & 31) * 4;   // B tile n offset

    const float* Aptr = A + (size_t)(brow + ar) * K + ak;
    const float* Bptr = B + (size_t)bkk * N + bcol + bn;

    float acc[8][8];
#pragma unroll
    for (int i = 0; i < 8; i++)
#pragma unroll
        for (int j = 0; j < 8; j++) acc[i][j] = 0.f;

    for (int k0 = 0; k0 < K; k0 += 8) {
        float4 av = *(const float4*)(Aptr + k0);
        float4 bv = *(const float4*)(Bptr + (size_t)k0 * N);
        __syncthreads();
        As[ak + 0][ar] = av.x; As[ak + 1][ar] = av.y;
        As[ak + 2][ar] = av.z; As[ak + 3][ar] = av.w;
        *(float4*)&Bs[bkk][bn] = bv;
        __syncthreads();
#pragma unroll
        for (int kk = 0; kk < 8; kk++) {
            float a[8], b[8];
            *(float4*)&a[0] = *(const float4*)&As[kk][ty * 4];
            *(float4*)&a[4] = *(const float4*)&As[kk][64 + ty * 4];
            *(float4*)&b[0] = *(const float4*)&Bs[kk][tx * 4];
            *(float4*)&b[4] = *(const float4*)&Bs[kk][64 + tx * 4];
#pragma unroll
            for (int i = 0; i < 8; i++)
#pragma unroll
                for (int j = 0; j < 8; j++)
                    acc[i][j] = fmaf(a[i], b[j], acc[i][j]);
        }
    }
#pragma unroll
    for (int i = 0; i < 8; i++) {
        int row = brow + ((i < 4) ? (ty * 4 + i) : (64 + ty * 4 + (i - 4)));
#pragma unroll
        for (int jq = 0; jq < 2; jq++) {
            int col = bcol + ((jq == 0) ? (tx * 4) : (64 + tx * 4));
            float4 o;
            o.x = acc[i][jq * 4 + 0] + b1[col + 0] + b2[col + 0];
            o.y = acc[i][jq * 4 + 1] + b1[col + 1] + b2[col + 1];
            o.z = acc[i][jq * 4 + 2] + b1[col + 2] + b2[col + 2];
            o.w = acc[i][jq * 4 + 3] + b1[col + 3] + b2[col + 3];
            *(float4*)&C[(size_t)row * N + col] = o;
        }
    }
}

// ---------------- persistent LSTM scan ----------------
// grid = 128 CTAs x 256 threads. CTA b owns units [8b, 8b+8).
// Warp w handles unit u = 8b + w: rows {u, H+u, 2H+u, 3H+u} of W_hh kept in
// registers (lane L holds k = 128c + 4L + [0..4), c = 0..7). One grid barrier
// per timestep via per-step atomic counters.
__device__ __forceinline__ float sigmoidf_(float x) {
    return 1.f / (1.f + expf(-x));
}

__global__ void __launch_bounds__(256, 1) lstm_scan_k(
    const float* __restrict__ Whh, const float* __restrict__ gx,
    float* __restrict__ seqout, unsigned* __restrict__ counts) {
    __shared__ float4 sh[HDIM / 4];
    const int tid  = threadIdx.x;
    const int lane = tid & 31;
    const int w    = tid >> 5;
    const int u    = blockIdx.x * 8 + w;

    // load persistent weights into registers (coalesced: lane-stride 16B)
    float4 wr[4][8];
#pragma unroll
    for (int g = 0; g < 4; g++) {
        const float* wp = Whh + (size_t)(g * HDIM + u) * HDIM + lane * 4;
#pragma unroll
        for (int c = 0; c < 8; c++) wr[g][c] = *(const float4*)(wp + c * 128);
    }

    float cst = 0.f;
    const float4* hsrc = (const float4*)g_zero;

    for (int t = 0; t < SEQ; t++) {
        // stage h_{t-1} into SMEM (L2-only load: fresh data from other SMs)
        sh[tid] = __ldcg(hsrc + tid);
        // prefetch gx for this step (consumed after the reduction)
        float gi = 0.f, gf = 0.f, gg = 0.f, go = 0.f;
        if (lane == 0) {
            const float* p = gx + (size_t)t * GDIM + u;
            gi = __ldg(p);
            gf = __ldg(p + HDIM);
            gg = __ldg(p + 2 * HDIM);
            go = __ldg(p + 3 * HDIM);
        }
        __syncthreads();

        float a0 = 0.f, a1 = 0.f, a2 = 0.f, a3 = 0.f;
#pragma unroll
        for (int c = 0; c < 8; c++) {
            float4 hv = sh[c * 32 + lane];
            a0 = fmaf(wr[0][c].x, hv.x, a0); a0 = fmaf(wr[0][c].y, hv.y, a0);
            a0 = fmaf(wr[0][c].z, hv.z, a0); a0 = fmaf(wr[0][c].w, hv.w, a0);
            a1 = fmaf(wr[1][c].x, hv.x, a1); a1 = fmaf(wr[1][c].y, hv.y, a1);
            a1 = fmaf(wr[1][c].z, hv.z, a1); a1 = fmaf(wr[1][c].w, hv.w, a1);
            a2 = fmaf(wr[2][c].x, hv.x, a2); a2 = fmaf(wr[2][c].y, hv.y, a2);
            a2 = fmaf(wr[2][c].z, hv.z, a2); a2 = fmaf(wr[2][c].w, hv.w, a2);
            a3 = fmaf(wr[3][c].x, hv.x, a3); a3 = fmaf(wr[3][c].y, hv.y, a3);
            a3 = fmaf(wr[3][c].z, hv.z, a3); a3 = fmaf(wr[3][c].w, hv.w, a3);
        }
#pragma unroll
        for (int s = 16; s > 0; s >>= 1) {
            a0 += __shfl_xor_sync(0xffffffffu, a0, s);
            a1 += __shfl_xor_sync(0xffffffffu, a1, s);
            a2 += __shfl_xor_sync(0xffffffffu, a2, s);
            a3 += __shfl_xor_sync(0xffffffffu, a3, s);
        }
        if (lane == 0) {
            float iv = sigmoidf_(a0 + gi);
            float fv = sigmoidf_(a1 + gf);
            float gv = tanhf(a2 + gg);
            float ov = sigmoidf_(a3 + go);
            cst = fmaf(fv, cst, iv * gv);
            seqout[(size_t)t * HDIM + u] = ov * tanhf(cst);
        }
        __syncthreads();
        // grid barrier for step t (all 128 CTAs resident -> no deadlock)
        if (tid == 0) {
            __threadfence();                 // publish this CTA's h stores
            atomicAdd(counts + t, 1u);
            while (*((volatile unsigned*)(counts + t)) < (unsigned)NB) { }
            __threadfence();                 // acquire other CTAs' h stores
        }
        __syncthreads();
        hsrc = (const float4*)(seqout + (size_t)t * HDIM);
    }
}

// ---------------- launch ----------------
extern "C" void kernel_launch(void* const* d_in, const int* in_sizes, int n_in,
                              void* d_out, int out_size) {
    const float* x    = (const float*)d_in[0];
    const float* Wih[3] = {(const float*)d_in[1], (const float*)d_in[5],  (const float*)d_in[9]};
    const float* Whh[3] = {(const float*)d_in[2], (const float*)d_in[6],  (const float*)d_in[10]};
    const float* bih[3] = {(const float*)d_in[3], (const float*)d_in[7],  (const float*)d_in[11]};
    const float* bhh[3] = {(const float*)d_in[4], (const float*)d_in[8],  (const float*)d_in[12]};
    const float* fcw  = (const float*)d_in[13];
    const float* fcb  = (const float*)d_in[14];
    float* out = (float*)d_out;

    float *gx, *seqA, *seqB, *Wt, *bz;
    unsigned* counts;
    cudaGetSymbolAddress((void**)&gx,     g_gx);
    cudaGetSymbolAddress((void**)&seqA,   g_seqA);
    cudaGetSymbolAddress((void**)&seqB,   g_seqB);
    cudaGetSymbolAddress((void**)&Wt,     g_Wt);
    cudaGetSymbolAddress((void**)&bz,     g_bzero);
    cudaGetSymbolAddress((void**)&counts, g_counts);

    const float* ins[3]  = {x, seqA, seqB};
    float*       outs[3] = {seqA, seqB, seqA};

    dim3 tb(32, 8);
    for (int l = 0; l < 3; l++) {
        transpose_k<<<dim3(HDIM / 32, GDIM / 32), tb>>>(Wih[l], Wt, GDIM, HDIM);
        sgemm_bias_k<<<dim3(GDIM / 128, SEQ / 128), 256>>>(
            ins[l], Wt, bih[l], bhh[l], gx, SEQ, GDIM, HDIM);
        zero_k<<<SEQ / 256, 256>>>(counts, SEQ);
        lstm_scan_k<<<NB, 256>>>(Whh[l], gx, outs[l], counts);
    }
    // FC head
    transpose_k<<<dim3(HDIM / 32, NCLS / 32), tb>>>(fcw, Wt, NCLS, HDIM);
    sgemm_bias_k<<<dim3(NCLS / 128, SEQ / 128), 256>>>(
        seqA, Wt, fcb, bz, out, SEQ, NCLS, HDIM);
}

// round 4
// speedup vs baseline: 1.2012x; 1.2012x over previous
#include <cuda_runtime.h>
#include <math.h>

#define SEQ  2048
#define HDIM 1024
#define GDIM 4096   // 4*H
#define NCLS 512
#define NB   128    // scan grid (<= SM count -> all resident)

// ---------------- scratch (static device globals; no allocation) -------------
__device__ float    g_gx[SEQ * GDIM];      // 32 MB: precomputed input gates
__device__ float    g_seqA[SEQ * HDIM];    // 8 MB: layer output ping
__device__ float    g_seqB[SEQ * HDIM];    // 8 MB: layer output pong
__device__ float    g_Wt[HDIM * GDIM];     // 16 MB: transposed weight (max size)
__device__ float    g_bzero[GDIM];         // stays zero (dummy 2nd bias)
__device__ unsigned g_counts[SEQ];         // per-step barrier counters

// ---------------- fast, overflow-safe activations ----------------------------
__device__ __forceinline__ float fast_sigmoid(float x) {
    return __fdividef(1.f, 1.f + __expf(-x));   // exp(inf)->inf -> 0 : safe
}
__device__ __forceinline__ float fast_tanh(float x) {
    float ax = fabsf(x);
    float e  = __expf(2.f * ax);
    float t  = 1.f - __fdividef(2.f, e + 1.f);  // e=inf -> 1
    return copysignf(t, x);
}

// ---------------- transpose: Wt[c][r] = W[r][c] -------------------------------
__global__ void transpose_k(const float* __restrict__ W, float* __restrict__ Wt,
                            int R, int C) {
    __shared__ float tile[32][33];
    int c0 = blockIdx.x * 32, r0 = blockIdx.y * 32;
    int x = threadIdx.x, y = threadIdx.y;
#pragma unroll
    for (int j = 0; j < 32; j += 8)
        tile[y + j][x] = W[(size_t)(r0 + y + j) * C + (c0 + x)];
    __syncthreads();
#pragma unroll
    for (int j = 0; j < 32; j += 8)
        Wt[(size_t)(c0 + y + j) * R + (r0 + x)] = tile[x][y + j];
}

// ---------------- zero barrier counters --------------------------------------
__global__ void zero_k(unsigned* p, int n) {
    int i = blockIdx.x * 256 + threadIdx.x;
    if (i < n) p[i] = 0;
}

// ---------------- SGEMM: C[M,N] = A[M,K] @ B[K,N] + b1[N] + b2[N] -------------
// BM=BN=128, BK=8, 256 threads, 8x8 per thread. (Round-1 known-good version.)
__global__ void __launch_bounds__(256) sgemm_bias_k(
    const float* __restrict__ A, const float* __restrict__ B,
    const float* __restrict__ b1, const float* __restrict__ b2,
    float* __restrict__ C, int M, int N, int K) {
    __shared__ float As[8][128];
    __shared__ float Bs[8][128];
    const int tid  = threadIdx.x;
    const int tx   = tid & 15;
    const int ty   = tid >> 4;
    const int brow = blockIdx.y * 128;
    const int bcol = blockIdx.x * 128;

    const int ar  = tid >> 1;
    const int ak  = (tid & 1) * 4;
    const int bkk = tid >> 5;
    const int bn  = (tid & 31) * 4;

    const float* Aptr = A + (size_t)(brow + ar) * K + ak;
    const float* Bptr = B + (size_t)bkk * N + bcol + bn;

    float acc[8][8];
#pragma unroll
    for (int i = 0; i < 8; i++)
#pragma unroll
        for (int j = 0; j < 8; j++) acc[i][j] = 0.f;

    for (int k0 = 0; k0 < K; k0 += 8) {
        float4 av = *(const float4*)(Aptr + k0);
        float4 bv = *(const float4*)(Bptr + (size_t)k0 * N);
        __syncthreads();
        As[ak + 0][ar] = av.x; As[ak + 1][ar] = av.y;
        As[ak + 2][ar] = av.z; As[ak + 3][ar] = av.w;
        *(float4*)&Bs[bkk][bn] = bv;
        __syncthreads();
#pragma unroll
        for (int kk = 0; kk < 8; kk++) {
            float a[8], b[8];
            *(float4*)&a[0] = *(const float4*)&As[kk][ty * 4];
            *(float4*)&a[4] = *(const float4*)&As[kk][64 + ty * 4];
            *(float4*)&b[0] = *(const float4*)&Bs[kk][tx * 4];
            *(float4*)&b[4] = *(const float4*)&Bs[kk][64 + tx * 4];
#pragma unroll
            for (int i = 0; i < 8; i++)
#pragma unroll
                for (int j = 0; j < 8; j++)
                    acc[i][j] = fmaf(a[i], b[j], acc[i][j]);
        }
    }
#pragma unroll
    for (int i = 0; i < 8; i++) {
        int row = brow + ((i < 4) ? (ty * 4 + i) : (64 + ty * 4 + (i - 4)));
#pragma unroll
        for (int jq = 0; jq < 2; jq++) {
            int col = bcol + ((jq == 0) ? (tx * 4) : (64 + tx * 4));
            float4 o;
            o.x = acc[i][jq * 4 + 0] + b1[col + 0] + b2[col + 0];
            o.y = acc[i][jq * 4 + 1] + b1[col + 1] + b2[col + 1];
            o.z = acc[i][jq * 4 + 2] + b1[col + 2] + b2[col + 2];
            o.w = acc[i][jq * 4 + 3] + b1[col + 3] + b2[col + 3];
            *(float4*)&C[(size_t)row * N + col] = o;
        }
    }
}

// ---------------- persistent LSTM scan (round-1 topology, acq/rel barrier) ----
// grid = 128 CTAs x 256 threads. CTA b owns units [8b, 8b+8); warp w -> unit
// u = 8b + w: rows {u, H+u, 2H+u, 3H+u} of W_hh in registers. One grid barrier
// per timestep: red.release.gpu publish + ld.acquire.gpu poll (after bar.sync,
// fence cumulativity covers the whole CTA's stores).
__global__ void __launch_bounds__(256, 1) lstm_scan_k(
    const float* __restrict__ Whh, const float* __restrict__ gx,
    float* __restrict__ seqout, unsigned* __restrict__ counts) {
    __shared__ float4 sh[HDIM / 4];
    const int tid  = threadIdx.x;
    const int lane = tid & 31;
    const int w    = tid >> 5;
    const int u    = blockIdx.x * 8 + w;

    // persistent weights in registers (coalesced: lane-stride 16B)
    float4 wr[4][8];
#pragma unroll
    for (int g = 0; g < 4; g++) {
        const float* wp = Whh + (size_t)(g * HDIM + u) * HDIM + lane * 4;
#pragma unroll
        for (int c = 0; c < 8; c++) wr[g][c] = *(const float4*)(wp + c * 128);
    }

    float cst = 0.f;
    const float4* hsrc = 0;   // set after step 0

    for (int t = 0; t < SEQ; t++) {
        // stage h_{t-1} into SMEM (L2 load: fresh data from other SMs)
        if (t == 0) sh[tid] = make_float4(0.f, 0.f, 0.f, 0.f);
        else        sh[tid] = __ldcg(hsrc + tid);

        // gx for this step: warp-broadcast load on all lanes (same addresses)
        const float* p = gx + (size_t)t * GDIM + u;
        float gi = __ldg(p);
        float gf = __ldg(p + HDIM);
        float gg = __ldg(p + 2 * HDIM);
        float go = __ldg(p + 3 * HDIM);
        __syncthreads();

        float a0 = 0.f, a1 = 0.f, a2 = 0.f, a3 = 0.f;
#pragma unroll
        for (int c = 0; c < 8; c++) {
            float4 hv = sh[c * 32 + lane];
            a0 = fmaf(wr[0][c].x, hv.x, a0); a0 = fmaf(wr[0][c].y, hv.y, a0);
            a0 = fmaf(wr[0][c].z, hv.z, a0); a0 = fmaf(wr[0][c].w, hv.w, a0);
            a1 = fmaf(wr[1][c].x, hv.x, a1); a1 = fmaf(wr[1][c].y, hv.y, a1);
            a1 = fmaf(wr[1][c].z, hv.z, a1); a1 = fmaf(wr[1][c].w, hv.w, a1);
            a2 = fmaf(wr[2][c].x, hv.x, a2); a2 = fmaf(wr[2][c].y, hv.y, a2);
            a2 = fmaf(wr[2][c].z, hv.z, a2); a2 = fmaf(wr[2][c].w, hv.w, a2);
            a3 = fmaf(wr[3][c].x, hv.x, a3); a3 = fmaf(wr[3][c].y, hv.y, a3);
            a3 = fmaf(wr[3][c].z, hv.z, a3); a3 = fmaf(wr[3][c].w, hv.w, a3);
        }
#pragma unroll
        for (int s = 16; s > 0; s >>= 1) {
            a0 += __shfl_xor_sync(0xffffffffu, a0, s);
            a1 += __shfl_xor_sync(0xffffffffu, a1, s);
            a2 += __shfl_xor_sync(0xffffffffu, a2, s);
            a3 += __shfl_xor_sync(0xffffffffu, a3, s);
        }
        // all lanes compute identical gate values (no divergence, MUFU fast path)
        float iv = fast_sigmoid(a0 + gi);
        float fv = fast_sigmoid(a1 + gf);
        float gv = fast_tanh(a2 + gg);
        float ov = fast_sigmoid(a3 + go);
        cst = fmaf(fv, cst, iv * gv);
        float h = ov * fast_tanh(cst);
        if (lane == 0) seqout[(size_t)t * HDIM + u] = h;

        __syncthreads();   // all 8 unit-stores of this CTA done before release
        if (tid == 0) {
            const unsigned* cnt = counts + t;
            asm volatile("red.release.gpu.global.add.u32 [%0], 1;"
                         :: "l"(cnt) : "memory");
            unsigned v;
            do {
                asm volatile("ld.acquire.gpu.global.u32 %0, [%1];"
                             : "=r"(v) : "l"(cnt) : "memory");
            } while (v < (unsigned)NB);
        }
        __syncthreads();   // acquire by tid0 + barrier orders the h reloads
        hsrc = (const float4*)(seqout + (size_t)t * HDIM);
    }
}

// ---------------- launch ----------------
extern "C" void kernel_launch(void* const* d_in, const int* in_sizes, int n_in,
                              void* d_out, int out_size) {
    const float* x      = (const float*)d_in[0];
    const float* Wih[3] = {(const float*)d_in[1], (const float*)d_in[5],  (const float*)d_in[9]};
    const float* Whh[3] = {(const float*)d_in[2], (const float*)d_in[6],  (const float*)d_in[10]};
    const float* bih[3] = {(const float*)d_in[3], (const float*)d_in[7],  (const float*)d_in[11]};
    const float* bhh[3] = {(const float*)d_in[4], (const float*)d_in[8],  (const float*)d_in[12]};
    const float* fcw    = (const float*)d_in[13];
    const float* fcb    = (const float*)d_in[14];
    float* out = (float*)d_out;

    float *gx, *seqA, *seqB, *Wt, *bz;
    unsigned* counts;
    cudaGetSymbolAddress((void**)&gx,     g_gx);
    cudaGetSymbolAddress((void**)&seqA,   g_seqA);
    cudaGetSymbolAddress((void**)&seqB,   g_seqB);
    cudaGetSymbolAddress((void**)&Wt,     g_Wt);
    cudaGetSymbolAddress((void**)&bz,     g_bzero);
    cudaGetSymbolAddress((void**)&counts, g_counts);

    const float* ins[3]  = {x, seqA, seqB};
    float*       outs[3] = {seqA, seqB, seqA};

    dim3 tb(32, 8);
    for (int l = 0; l < 3; l++) {
        transpose_k<<<dim3(HDIM / 32, GDIM / 32), tb>>>(Wih[l], Wt, GDIM, HDIM);
        sgemm_bias_k<<<dim3(GDIM / 128, SEQ / 128), 256>>>(
            ins[l], Wt, bih[l], bhh[l], gx, SEQ, GDIM, HDIM);
        zero_k<<<SEQ / 256, 256>>>(counts, SEQ);
        lstm_scan_k<<<NB, 256>>>(Whh[l], gx, outs[l], counts);
    }
    // FC head
    transpose_k<<<dim3(HDIM / 32, NCLS / 32), tb>>>(fcw, Wt, NCLS, HDIM);
    sgemm_bias_k<<<dim3(NCLS / 128, SEQ / 128), 256>>>(
        seqA, Wt, fcb, bz, out, SEQ, NCLS, HDIM);
}